// round 3
// baseline (speedup 1.0000x reference)
#include <cuda_runtime.h>

// DipolePredictorE3NN
// Inputs (metadata order):
//   d_in[0] feats  [B, N, 7]  f32
//   d_in[1] coors  [B, N, 3]  f32
//   d_in[2] adj_mat[B, N, N]  bool  (UNUSED — never read)
//   d_in[3] W_tp   [7]        f32
//   d_in[4] W1     [128, 3]   f32
//   d_in[5] b1     [128]      f32
//   d_in[6] W2     [3, 128]   f32
//   d_in[7] b2     [3]        f32
// Output: [B, 3] f32
//
// out[b] = MLP( (1/sqrt(7)) * mean_n( (feats[b,n,:]·W_tp) * coors[b,n,:] ) )

#define NS 7
#define HID 128
#define THREADS 128   // each thread owns 4 consecutive nodes -> covers N=512

__global__ __launch_bounds__(THREADS)
void dipole_kernel(const float* __restrict__ feats,
                   const float* __restrict__ coors,
                   const float* __restrict__ W_tp,
                   const float* __restrict__ W1,
                   const float* __restrict__ b1,
                   const float* __restrict__ W2,
                   const float* __restrict__ b2,
                   float* __restrict__ out,
                   int N)
{
    const int b    = blockIdx.x;
    const int tid  = threadIdx.x;
    const int lane = tid & 31;
    const int wid  = tid >> 5;

    float w[NS];
#pragma unroll
    for (int i = 0; i < NS; i++) w[i] = __ldg(&W_tp[i]);

    const float* fb = feats + (size_t)b * N * NS;
    const float* cb = coors + (size_t)b * N * 3;

    float ax = 0.f, ay = 0.f, az = 0.f;

    const int n4_count = N >> 2;           // groups of 4 nodes
    for (int g = tid; g < n4_count; g += THREADS) {
        // 4 nodes x 7 feats = 28 floats = 7 float4 (base offset g*112 B, 16B-aligned)
        const float4* f4 = reinterpret_cast<const float4*>(fb + (size_t)g * 4 * NS);
        float ff[28];
#pragma unroll
        for (int i = 0; i < 7; i++) {
            float4 v = __ldg(&f4[i]);
            ff[i * 4 + 0] = v.x; ff[i * 4 + 1] = v.y;
            ff[i * 4 + 2] = v.z; ff[i * 4 + 3] = v.w;
        }
        // 4 nodes x 3 coors = 12 floats = 3 float4 (base offset g*48 B, 16B-aligned)
        const float4* c4 = reinterpret_cast<const float4*>(cb + (size_t)g * 4 * 3);
        float cc[12];
#pragma unroll
        for (int i = 0; i < 3; i++) {
            float4 v = __ldg(&c4[i]);
            cc[i * 4 + 0] = v.x; cc[i * 4 + 1] = v.y;
            cc[i * 4 + 2] = v.z; cc[i * 4 + 3] = v.w;
        }
#pragma unroll
        for (int j = 0; j < 4; j++) {
            float s = 0.f;
#pragma unroll
            for (int i = 0; i < NS; i++) s = fmaf(ff[j * NS + i], w[i], s);
            ax = fmaf(s, cc[j * 3 + 0], ax);
            ay = fmaf(s, cc[j * 3 + 1], ay);
            az = fmaf(s, cc[j * 3 + 2], az);
        }
    }
    // scalar tail for N % 4 (absent for N=512)
    for (int n = (n4_count << 2) + tid; n < N; n += THREADS) {
        const float* fr = fb + (size_t)n * NS;
        float s = 0.f;
#pragma unroll
        for (int i = 0; i < NS; i++) s = fmaf(fr[i], w[i], s);
        const float* cr = cb + (size_t)n * 3;
        ax = fmaf(s, cr[0], ax);
        ay = fmaf(s, cr[1], ay);
        az = fmaf(s, cr[2], az);
    }

    // Warp reduce
#pragma unroll
    for (int o = 16; o > 0; o >>= 1) {
        ax += __shfl_down_sync(0xFFFFFFFFu, ax, o);
        ay += __shfl_down_sync(0xFFFFFFFFu, ay, o);
        az += __shfl_down_sync(0xFFFFFFFFu, az, o);
    }

    __shared__ float sx[THREADS / 32], sy[THREADS / 32], sz[THREADS / 32];
    if (lane == 0) { sx[wid] = ax; sy[wid] = ay; sz[wid] = az; }
    __syncthreads();

    if (wid == 0) {
        constexpr int NW = THREADS / 32;
        float rx = (lane < NW) ? sx[lane] : 0.f;
        float ry = (lane < NW) ? sy[lane] : 0.f;
        float rz = (lane < NW) ? sz[lane] : 0.f;
#pragma unroll
        for (int o = NW >> 1; o > 0; o >>= 1) {
            rx += __shfl_down_sync(0xFFFFFFFFu, rx, o);
            ry += __shfl_down_sync(0xFFFFFFFFu, ry, o);
            rz += __shfl_down_sync(0xFFFFFFFFu, rz, o);
        }
        // alpha = 1/sqrt(7); mean over N
        const float scale = 0.3779644730092272f / (float)N;
        float g0 = __shfl_sync(0xFFFFFFFFu, rx, 0) * scale;
        float g1 = __shfl_sync(0xFFFFFFFFu, ry, 0) * scale;
        float g2 = __shfl_sync(0xFFFFFFFFu, rz, 0) * scale;

        // MLP: out = W2 @ relu(W1 @ g + b1) + b2 ; each lane owns 4 hidden units
        float o0 = 0.f, o1 = 0.f, o2 = 0.f;
#pragma unroll
        for (int r = 0; r < HID / 32; r++) {
            int j = lane + r * 32;
            float h = fmaf(W1[j * 3 + 0], g0,
                      fmaf(W1[j * 3 + 1], g1,
                      fmaf(W1[j * 3 + 2], g2, b1[j])));
            h = fmaxf(h, 0.f);
            o0 = fmaf(W2[0 * HID + j], h, o0);
            o1 = fmaf(W2[1 * HID + j], h, o1);
            o2 = fmaf(W2[2 * HID + j], h, o2);
        }
#pragma unroll
        for (int o = 16; o > 0; o >>= 1) {
            o0 += __shfl_down_sync(0xFFFFFFFFu, o0, o);
            o1 += __shfl_down_sync(0xFFFFFFFFu, o1, o);
            o2 += __shfl_down_sync(0xFFFFFFFFu, o2, o);
        }
        if (lane == 0) {
            out[b * 3 + 0] = o0 + b2[0];
            out[b * 3 + 1] = o1 + b2[1];
            out[b * 3 + 2] = o2 + b2[2];
        }
    }
}

extern "C" void kernel_launch(void* const* d_in, const int* in_sizes, int n_in,
                              void* d_out, int out_size)
{
    const float* feats = (const float*)d_in[0];
    const float* coors = (const float*)d_in[1];
    // d_in[2] = adj_mat, intentionally unused
    const float* W_tp  = (const float*)d_in[3];
    const float* W1    = (const float*)d_in[4];
    const float* b1    = (const float*)d_in[5];
    const float* W2    = (const float*)d_in[6];
    const float* b2    = (const float*)d_in[7];
    float* out = (float*)d_out;

    const int B = out_size / 3;                 // output is [B, 3]
    const int N = in_sizes[1] / (B * 3);        // coors is [B, N, 3]

    dipole_kernel<<<B, THREADS>>>(feats, coors, W_tp, W1, b1, W2, b2, out, N);
}

// round 4
// speedup vs baseline: 1.0119x; 1.0119x over previous
#include <cuda_runtime.h>
#include <cstdint>

// DipolePredictorE3NN
//   d_in[0] feats  [B, N, 7]  f32
//   d_in[1] coors  [B, N, 3]  f32
//   d_in[2] adj_mat (UNUSED)
//   d_in[3] W_tp [7], d_in[4] W1 [128,3], d_in[5] b1 [128],
//   d_in[6] W2 [3,128], d_in[7] b2 [3]
// Output: [B, 3] f32
//
// R3 insight: v2 was LSU-issue-bound (1.31M LDG x 1.82cyc/SM-LDG ~= 8.5us).
// Load each CTA's 20480B tile via 2 cp.async.bulk (TMA pipe) instead, then LDS.

#define NS 7
#define HID 128
#define THREADS 128
#define N_FIXED 512
#define FEATS_BYTES (N_FIXED * NS * 4)   // 14336
#define COORS_BYTES (N_FIXED * 3 * 4)    // 6144

__device__ __forceinline__ uint32_t smem_u32(const void* p) {
    uint32_t a;
    asm("{ .reg .u64 t; cvta.to.shared.u64 t, %1; cvt.u32.u64 %0, t; }"
        : "=r"(a) : "l"(p));
    return a;
}

// ---------- shared epilogue: block-reduce 3-vector, warp0 runs MLP ----------
__device__ __forceinline__ void reduce_and_mlp(
    float ax, float ay, float az, int N,
    const float* __restrict__ W1, const float* __restrict__ b1,
    const float* __restrict__ W2, const float* __restrict__ b2,
    float* __restrict__ out, int b)
{
    const int lane = threadIdx.x & 31;
    const int wid  = threadIdx.x >> 5;
#pragma unroll
    for (int o = 16; o > 0; o >>= 1) {
        ax += __shfl_down_sync(0xFFFFFFFFu, ax, o);
        ay += __shfl_down_sync(0xFFFFFFFFu, ay, o);
        az += __shfl_down_sync(0xFFFFFFFFu, az, o);
    }
    __shared__ float sx[THREADS / 32], sy[THREADS / 32], sz[THREADS / 32];
    if (lane == 0) { sx[wid] = ax; sy[wid] = ay; sz[wid] = az; }
    __syncthreads();
    if (wid == 0) {
        constexpr int NW = THREADS / 32;
        float rx = (lane < NW) ? sx[lane] : 0.f;
        float ry = (lane < NW) ? sy[lane] : 0.f;
        float rz = (lane < NW) ? sz[lane] : 0.f;
#pragma unroll
        for (int o = NW >> 1; o > 0; o >>= 1) {
            rx += __shfl_down_sync(0xFFFFFFFFu, rx, o);
            ry += __shfl_down_sync(0xFFFFFFFFu, ry, o);
            rz += __shfl_down_sync(0xFFFFFFFFu, rz, o);
        }
        const float scale = 0.3779644730092272f / (float)N;  // 1/sqrt(7)/N
        float g0 = __shfl_sync(0xFFFFFFFFu, rx, 0) * scale;
        float g1 = __shfl_sync(0xFFFFFFFFu, ry, 0) * scale;
        float g2 = __shfl_sync(0xFFFFFFFFu, rz, 0) * scale;
        float o0 = 0.f, o1 = 0.f, o2 = 0.f;
#pragma unroll
        for (int r = 0; r < HID / 32; r++) {
            int j = lane + r * 32;
            float h = fmaf(W1[j * 3 + 0], g0,
                      fmaf(W1[j * 3 + 1], g1,
                      fmaf(W1[j * 3 + 2], g2, b1[j])));
            h = fmaxf(h, 0.f);
            o0 = fmaf(W2[0 * HID + j], h, o0);
            o1 = fmaf(W2[1 * HID + j], h, o1);
            o2 = fmaf(W2[2 * HID + j], h, o2);
        }
#pragma unroll
        for (int o = 16; o > 0; o >>= 1) {
            o0 += __shfl_down_sync(0xFFFFFFFFu, o0, o);
            o1 += __shfl_down_sync(0xFFFFFFFFu, o1, o);
            o2 += __shfl_down_sync(0xFFFFFFFFu, o2, o);
        }
        if (lane == 0) {
            out[b * 3 + 0] = o0 + b2[0];
            out[b * 3 + 1] = o1 + b2[1];
            out[b * 3 + 2] = o2 + b2[2];
        }
    }
}

// ---------- fast path: N==512, bulk-copy tile to smem, compute from LDS ----------
__global__ __launch_bounds__(THREADS)
void dipole_tma_kernel(const float* __restrict__ feats,
                       const float* __restrict__ coors,
                       const float* __restrict__ W_tp,
                       const float* __restrict__ W1,
                       const float* __restrict__ b1,
                       const float* __restrict__ W2,
                       const float* __restrict__ b2,
                       float* __restrict__ out)
{
    __shared__ __align__(16) float s_feats[N_FIXED * NS];  // 14336 B
    __shared__ __align__(16) float s_coors[N_FIXED * 3];   // 6144 B
    __shared__ __align__(8)  uint64_t s_mbar;

    const int b   = blockIdx.x;
    const int tid = threadIdx.x;

    uint32_t mbar = smem_u32(&s_mbar);

    if (tid == 0) {
        asm volatile("mbarrier.init.shared.b64 [%0], 1;" :: "r"(mbar) : "memory");
    }
    __syncthreads();

    if (tid == 0) {
        asm volatile("mbarrier.arrive.expect_tx.shared.b64 _, [%0], %1;"
                     :: "r"(mbar), "r"((uint32_t)(FEATS_BYTES + COORS_BYTES)) : "memory");
        const char* gf = (const char*)(feats + (size_t)b * N_FIXED * NS);
        const char* gc = (const char*)(coors + (size_t)b * N_FIXED * 3);
        asm volatile(
            "cp.async.bulk.shared::cta.global.mbarrier::complete_tx::bytes "
            "[%0], [%1], %2, [%3];"
            :: "r"(smem_u32(s_feats)), "l"(gf), "r"((uint32_t)FEATS_BYTES), "r"(mbar)
            : "memory");
        asm volatile(
            "cp.async.bulk.shared::cta.global.mbarrier::complete_tx::bytes "
            "[%0], [%1], %2, [%3];"
            :: "r"(smem_u32(s_coors)), "l"(gc), "r"((uint32_t)COORS_BYTES), "r"(mbar)
            : "memory");
    }

    // Broadcast TP weights while the copy is in flight.
    float w[NS];
#pragma unroll
    for (int i = 0; i < NS; i++) w[i] = __ldg(&W_tp[i]);

    // Wait for bulk-copy completion (phase 0).
    {
        uint32_t done;
        asm volatile(
            "{ .reg .pred p; mbarrier.try_wait.parity.shared.b64 p, [%1], 0; "
            "selp.b32 %0, 1, 0, p; }"
            : "=r"(done) : "r"(mbar) : "memory");
        if (!done) {
            asm volatile(
                "{ .reg .pred P1;\n"
                "W_%=: mbarrier.try_wait.parity.shared.b64 P1, [%0], 0, 0x989680;\n"
                "@P1 bra.uni D_%=;\n"
                "bra.uni W_%=;\n"
                "D_%=: }"
                :: "r"(mbar) : "memory");
        }
    }

    // Each thread owns group g = tid : 4 consecutive nodes, all reads from smem.
    const int g = tid;
    float ax = 0.f, ay = 0.f, az = 0.f;
    {
        const float4* f4 = reinterpret_cast<const float4*>(s_feats + g * 4 * NS);
        float ff[28];
#pragma unroll
        for (int i = 0; i < 7; i++) {
            float4 v = f4[i];
            ff[i * 4 + 0] = v.x; ff[i * 4 + 1] = v.y;
            ff[i * 4 + 2] = v.z; ff[i * 4 + 3] = v.w;
        }
        const float4* c4 = reinterpret_cast<const float4*>(s_coors + g * 4 * 3);
        float cc[12];
#pragma unroll
        for (int i = 0; i < 3; i++) {
            float4 v = c4[i];
            cc[i * 4 + 0] = v.x; cc[i * 4 + 1] = v.y;
            cc[i * 4 + 2] = v.z; cc[i * 4 + 3] = v.w;
        }
#pragma unroll
        for (int j = 0; j < 4; j++) {
            float s = 0.f;
#pragma unroll
            for (int i = 0; i < NS; i++) s = fmaf(ff[j * NS + i], w[i], s);
            ax = fmaf(s, cc[j * 3 + 0], ax);
            ay = fmaf(s, cc[j * 3 + 1], ay);
            az = fmaf(s, cc[j * 3 + 2], az);
        }
    }

    reduce_and_mlp(ax, ay, az, N_FIXED, W1, b1, W2, b2, out, b);
}

// ---------- generic fallback (any N): previous LDG kernel ----------
__global__ __launch_bounds__(THREADS)
void dipole_ldg_kernel(const float* __restrict__ feats,
                       const float* __restrict__ coors,
                       const float* __restrict__ W_tp,
                       const float* __restrict__ W1,
                       const float* __restrict__ b1,
                       const float* __restrict__ W2,
                       const float* __restrict__ b2,
                       float* __restrict__ out,
                       int N)
{
    const int b   = blockIdx.x;
    const int tid = threadIdx.x;
    float w[NS];
#pragma unroll
    for (int i = 0; i < NS; i++) w[i] = __ldg(&W_tp[i]);
    const float* fb = feats + (size_t)b * N * NS;
    const float* cb = coors + (size_t)b * N * 3;
    float ax = 0.f, ay = 0.f, az = 0.f;
    for (int n = tid; n < N; n += THREADS) {
        const float* fr = fb + (size_t)n * NS;
        float s = 0.f;
#pragma unroll
        for (int i = 0; i < NS; i++) s = fmaf(fr[i], w[i], s);
        const float* cr = cb + (size_t)n * 3;
        ax = fmaf(s, cr[0], ax);
        ay = fmaf(s, cr[1], ay);
        az = fmaf(s, cr[2], az);
    }
    reduce_and_mlp(ax, ay, az, N, W1, b1, W2, b2, out, b);
}

extern "C" void kernel_launch(void* const* d_in, const int* in_sizes, int n_in,
                              void* d_out, int out_size)
{
    const float* feats = (const float*)d_in[0];
    const float* coors = (const float*)d_in[1];
    // d_in[2] = adj_mat, intentionally unused
    const float* W_tp  = (const float*)d_in[3];
    const float* W1    = (const float*)d_in[4];
    const float* b1    = (const float*)d_in[5];
    const float* W2    = (const float*)d_in[6];
    const float* b2    = (const float*)d_in[7];
    float* out = (float*)d_out;

    const int B = out_size / 3;           // output [B, 3]
    const int N = in_sizes[1] / (B * 3);  // coors [B, N, 3]

    if (N == N_FIXED) {
        dipole_tma_kernel<<<B, THREADS>>>(feats, coors, W_tp, W1, b1, W2, b2, out);
    } else {
        dipole_ldg_kernel<<<B, THREADS>>>(feats, coors, W_tp, W1, b1, W2, b2, out, N);
    }
}